// round 2
// baseline (speedup 1.0000x reference)
#include <cuda_runtime.h>

// Signature-kernel MMD, fused single-kernel version.
// x,y: (32, 64, 4) fp32. SIGMA=1, DYADIC_ORDER=1 -> coarse inc 63x63, M=126.
// One warp per path-pair. Streaming gram (registers) -> folded inc table in smem
// -> antidiagonal Goursat PDE (4 cells/lane). Symmetric xx/yy computed once
// (weight 2). Last-block deterministic reduction (no second kernel).

#define BSZ 32
#define LEN 64
#define RS  64                     // inc row stride (floats)
#define BUFF (63*RS)               // 4032 floats per warp
#define NTRI ((BSZ*(BSZ+1))/2)     // 528
#define NTASKS (2*NTRI + BSZ*BSZ)  // 2080
#define WPC 2
#define NBLK ((NTASKS + WPC - 1) / WPC)   // 1040

__device__ float g_partial[NTASKS];
__device__ unsigned int g_count;   // zero-init; reset by reducer each run

__global__ void __launch_bounds__(32*WPC)
sig_kernel(const float* __restrict__ x, const float* __restrict__ y,
           float* __restrict__ out)
{
    extern __shared__ float smem[];
    const int lane = threadIdx.x & 31;
    const int wid  = threadIdx.x >> 5;
    const int task = blockIdx.x * WPC + wid;

    float* buf = smem + wid * BUFF;   // rows 0..62 hold 0.25*inc_coarse - 1

    // ---- decode task -> pair pointers + weight ----
    const float *pa, *pb;
    float weight;
    {
        int t = task;
        if (t < 2*NTRI) {
            const float* base = (t < NTRI) ? x : y;
            if (t >= NTRI) t -= NTRI;
            int a = 0;
            while (t >= (BSZ - a)) { t -= (BSZ - a); ++a; }
            int b = a + t;
            pa = base + a*(LEN*4);
            pb = base + b*(LEN*4);
            weight = (a == b ? 1.0f : 2.0f) * (1.0f/1024.0f);
        } else {
            t -= 2*NTRI;
            pa = x + (t >> 5)*(LEN*4);
            pb = y + (t & 31)*(LEN*4);
            weight = -2.0f/1024.0f;
        }
    }

    // ---- streaming RBF gram + second differences (fused, folded) ----
    // Lane owns gram columns j0=2*lane, j0+1. Row u of gram lives in regs only.
    const int j0 = lane << 1;
    const float4 b0 = __ldg(reinterpret_cast<const float4*>(pb + 4*j0));
    const float4 b1 = __ldg(reinterpret_cast<const float4*>(pb + 4*j0 + 4));

    float g0p, g1p;
    {
        float4 a = __ldg(reinterpret_cast<const float4*>(pa));
        float d0x=a.x-b0.x, d0y=a.y-b0.y, d0z=a.z-b0.z, d0w=a.w-b0.w;
        float d1x=a.x-b1.x, d1y=a.y-b1.y, d1z=a.z-b1.z, d1w=a.w-b1.w;
        g0p = __expf(-0.5f*(d0x*d0x + d0y*d0y + d0z*d0z + d0w*d0w));
        g1p = __expf(-0.5f*(d1x*d1x + d1y*d1y + d1z*d1z + d1w*d1w));
    }
    #pragma unroll 4
    for (int u = 1; u < LEN; ++u) {
        float4 a = __ldg(reinterpret_cast<const float4*>(pa + 4*u));
        float d0x=a.x-b0.x, d0y=a.y-b0.y, d0z=a.z-b0.z, d0w=a.w-b0.w;
        float d1x=a.x-b1.x, d1y=a.y-b1.y, d1z=a.z-b1.z, d1w=a.w-b1.w;
        float g0 = __expf(-0.5f*(d0x*d0x + d0y*d0y + d0z*d0z + d0w*d0w));
        float g1 = __expf(-0.5f*(d1x*d1x + d1y*d1y + d1z*d1z + d1w*d1w));
        float t0 = g0 - g0p;
        float t1 = g1 - g1p;
        float tn = __shfl_down_sync(0xffffffffu, t0, 1);  // t at col j0+2
        float r0 = fmaf(0.25f, t1 - t0, -1.0f);           // inc col j0
        float r1 = fmaf(0.25f, tn - t1, -1.0f);           // inc col j0+1 (lane31: pad)
        *reinterpret_cast<float2*>(buf + (u-1)*RS + j0) = make_float2(r0, r1);
        g0p = g0; g1p = g1;
    }
    __syncwarp();

    // ---- Goursat PDE, antidiagonal wavefront ----
    // Grid 127x127, diagonals d=0..252, lane holds i = 4*lane + k.
    const int i0 = lane << 2;
    float P2[4], P1[4];
    int rowoff[4];
    bool validi[4];
    #pragma unroll
    for (int k = 0; k < 4; ++k) {
        int i = i0 + k;
        P2[k] = (i == 0) ? 1.0f : 0.0f;
        P1[k] = (i <= 1) ? 1.0f : 0.0f;
        int im = (i < 1) ? 1 : i;
        int r  = (im - 1) >> 1;
        if (r > 62) r = 62;              // clamp (i=127 cells are masked anyway)
        rowoff[k] = r * RS;
        validi[k] = (i >= 1) && (i <= 126);
    }
    const bool isL0 = (lane == 0);

    auto step = [&](int d, float (&Pw)[4], const float (&Pr)[4]) {
        float p1top = __shfl_up_sync(0xffffffffu, Pr[3], 1);
        float p2top = __shfl_up_sync(0xffffffffu, Pw[3], 1);
        float o0 = Pw[0], o1 = Pw[1], o2 = Pw[2];
        int e = d - i0 - 1;                  // ek = j-1 for cell k
        #pragma unroll
        for (int k = 0; k < 4; ++k) {
            int ek = e - k;
            float lp1 = (k == 0) ? p1top : Pr[k-1];
            float lp2;
            if      (k == 0) lp2 = p2top;
            else if (k == 1) lp2 = o0;
            else if (k == 2) lp2 = o1;
            else             lp2 = o2;
            float incm1 = buf[rowoff[k] + ((ek >> 1) & 63)];  // masked, in-bounds
            float val = fmaf(lp2, incm1, lp1) + Pr[k];
            bool interior = validi[k] && ((unsigned)ek < 126u);
            float cc = interior ? val : ((ek == -1) ? 1.0f : 0.0f);
            if (k == 0) { if (isL0) cc = 1.0f; }
            Pw[k] = cc;
        }
    };

    for (int d = 2; d < 252; d += 2) {
        step(d,   P2, P1);
        step(d+1, P1, P2);
    }
    step(252, P2, P1);

    float res = __shfl_sync(0xffffffffu, P2[2], 31);   // K[126,126]
    if (lane == 0) g_partial[task] = res * weight;

    // ---- last-block deterministic reduction ----
    __threadfence();
    __syncthreads();
    __shared__ unsigned int sticket;
    if (threadIdx.x == 0) sticket = atomicAdd(&g_count, 1u);
    __syncthreads();
    if (sticket == (unsigned)(gridDim.x - 1)) {
        double s = 0.0;
        for (int i = threadIdx.x; i < NTASKS; i += 32*WPC)
            s += (double)__ldcg(&g_partial[i]);
        double* ds = reinterpret_cast<double*>(smem);
        ds[threadIdx.x] = s;
        __syncthreads();
        for (int w = (32*WPC)/2; w > 0; w >>= 1) {
            if (threadIdx.x < w) ds[threadIdx.x] += ds[threadIdx.x + w];
            __syncthreads();
        }
        if (threadIdx.x == 0) {
            out[0] = (float)ds[0];
            g_count = 0;                  // re-arm for next graph replay
        }
    }
}

extern "C" void kernel_launch(void* const* d_in, const int* in_sizes, int n_in,
                              void* d_out, int out_size)
{
    const float* x = (const float*)d_in[0];
    const float* y = (const float*)d_in[1];
    (void)in_sizes; (void)n_in; (void)out_size;

    // Maximize smem carveout so 7 CTAs (14 warps) fit per SM.
    cudaFuncSetAttribute(sig_kernel,
                         cudaFuncAttributePreferredSharedMemoryCarveout, 100);

    const size_t shmem = (size_t)WPC * BUFF * sizeof(float);  // 32256 B
    sig_kernel<<<NBLK, 32*WPC, shmem>>>(x, y, (float*)d_out);
}

// round 3
// speedup vs baseline: 1.4604x; 1.4604x over previous
#include <cuda_runtime.h>

// Signature-kernel MMD, masking-free wavefront PDE.
// x,y: (32,64,4) fp32. Coarse inc 63x63 (stored as 0.25*inc-1), refined M=126.
// One warp per path-pair; 4 PDE cells/lane along antidiagonals.
// Out-of-range cells self-maintain (0 / garbage that never reaches valid cells),
// so the inner loop is pure LDS+FFMA+FADD+SHFL with pointer bumps.

#define BSZ 32
#define LEN 64
#define NTRI ((BSZ*(BSZ+1))/2)     // 528
#define NTASKS (2*NTRI + BSZ*BSZ)  // 2080
#define WPC 2
#define NBLK ((NTASKS + WPC - 1) / WPC)

#define OSZ (31*65)                // odd coarse rows 1,3,..,61
#define ESZ (32*65)                // even coarse rows 0,2,..,62
#define GUARD 16
#define WSTRIDE 4112               // GUARD + 4096 (OSZ+ESZ=4095, +1 pad)

__device__ float g_partial[NTASKS];
__device__ unsigned int g_count;   // zero-init; reducer re-arms it

__global__ void __launch_bounds__(32*WPC)
sig_kernel(const float* __restrict__ x, const float* __restrict__ y,
           float* __restrict__ out)
{
    extern __shared__ float smem[];
    const int lane = threadIdx.x & 31;
    const int wid  = threadIdx.x >> 5;
    const int task = blockIdx.x * WPC + wid;

    float* warpbase = smem + wid * WSTRIDE;
    float* Ob = warpbase + GUARD;      // odd coarse rows, stride 65
    float* Eb = Ob + OSZ;              // even coarse rows, stride 65

    // Zero own region + guard: every stray PDE read must return a FINITE value.
    {
        float4* z = reinterpret_cast<float4*>(warpbase);
        for (int i = lane; i < WSTRIDE/4; i += 32)
            z[i] = make_float4(0.f, 0.f, 0.f, 0.f);
    }

    // ---- decode task -> pair pointers + weight ----
    const float *pa, *pb;
    float weight;
    {
        int t = task;
        if (t < 2*NTRI) {
            const float* base = (t < NTRI) ? x : y;
            if (t >= NTRI) t -= NTRI;
            int a = 0;
            while (t >= (BSZ - a)) { t -= (BSZ - a); ++a; }
            int b = a + t;
            pa = base + a*(LEN*4);
            pb = base + b*(LEN*4);
            weight = (a == b ? 1.0f : 2.0f) * (1.0f/1024.0f);
        } else {
            t -= 2*NTRI;
            pa = x + (t >> 5)*(LEN*4);
            pb = y + (t & 31)*(LEN*4);
            weight = -2.0f/1024.0f;
        }
    }

    // ---- streaming RBF gram + folded second differences ----
    // Lane owns gram cols j0=2*lane, j0+1; writes 0.25*inc-1 into O/E layout.
    const int j0 = lane << 1;
    const float4 b0 = __ldg(reinterpret_cast<const float4*>(pb + 4*j0));
    const float4 b1 = __ldg(reinterpret_cast<const float4*>(pb + 4*j0 + 4));

    float g0p, g1p;
    {
        float4 a = __ldg(reinterpret_cast<const float4*>(pa));
        float d0x=a.x-b0.x, d0y=a.y-b0.y, d0z=a.z-b0.z, d0w=a.w-b0.w;
        float d1x=a.x-b1.x, d1y=a.y-b1.y, d1z=a.z-b1.z, d1w=a.w-b1.w;
        g0p = __expf(-0.5f*(d0x*d0x + d0y*d0y + d0z*d0z + d0w*d0w));
        g1p = __expf(-0.5f*(d1x*d1x + d1y*d1y + d1z*d1z + d1w*d1w));
    }
    #pragma unroll 4
    for (int u = 1; u < LEN; ++u) {
        float4 a = __ldg(reinterpret_cast<const float4*>(pa + 4*u));
        float d0x=a.x-b0.x, d0y=a.y-b0.y, d0z=a.z-b0.z, d0w=a.w-b0.w;
        float d1x=a.x-b1.x, d1y=a.y-b1.y, d1z=a.z-b1.z, d1w=a.w-b1.w;
        float g0 = __expf(-0.5f*(d0x*d0x + d0y*d0y + d0z*d0z + d0w*d0w));
        float g1 = __expf(-0.5f*(d1x*d1x + d1y*d1y + d1z*d1z + d1w*d1w));
        float t0 = g0 - g0p;
        float t1 = g1 - g1p;
        float tn = __shfl_down_sync(0xffffffffu, t0, 1);   // t at col j0+2
        float r0 = fmaf(0.25f, t1 - t0, -1.0f);            // inc col j0
        float r1 = fmaf(0.25f, tn - t1, -1.0f);            // inc col j0+1
        int v = u - 1;
        float* wp = ((v & 1) ? Ob : Eb) + (v >> 1) * 65 + j0;
        wp[0] = r0; wp[1] = r1;
        g0p = g0; g1p = g1;
    }
    __syncwarp();

    // ---- Goursat PDE, antidiagonal wavefront, masking-free ----
    // Lane holds cells i = 4*lane + k, k=0..3. Per cell, coarse row is fixed
    // with fixed parity (k0,k3 -> odd rows; k1,k2 -> even rows); column index
    // is c0_k + m, so a single pointer bump per iteration suffices.
    const float* p0 = Ob + ((lane == 0) ? 0 : (63*lane - 65));
    const float* p1 = Eb + 63*lane;
    const float* p2 = p1 - 1;
    const float* p3 = Ob + 63*lane - 1;

    // A* = diagonal d-2, B* = diagonal d-1 registers
    float A0 = (lane==0) ? 1.f : 0.f, A1 = 0.f, A2 = 0.f, A3 = 0.f;   // diag 0
    float B0 = (lane==0) ? 1.f : 0.f, B1 = B0,  B2 = 0.f, B3 = 0.f;   // diag 1
    const bool isL0 = (lane == 0);

    #pragma unroll 5
    for (int m = 0; m < 125; ++m) {
        // diag d = 2m+2
        float sh1 = __shfl_up_sync(0xffffffffu, B3, 1);   // up   for k0
        float sh2 = __shfl_up_sync(0xffffffffu, A3, 1);   // diag for k0
        float a0A = p0[0], a0B = p0[1];
        float a1  = p1[0];        // also equals p2[1] (shared by B-step k2)
        float a2  = p2[0];
        float a3  = p3[0];        // shared by both half-steps of k3
        float v0 = fmaf(sh2, a0A, sh1) + B0;  if (isL0) v0 = 1.f;
        float v1 = fmaf(A0, a1, B0) + B1;
        float v2 = fmaf(A1, a2, B1) + B2;
        float v3 = fmaf(A2, a3, B2) + B3;
        // diag d+1 = 2m+3   (sh1 doubles as k0's diag operand: same shfl(B3))
        float sh1b = __shfl_up_sync(0xffffffffu, v3, 1);
        float w0 = fmaf(sh1, a0B, sh1b) + v0; if (isL0) w0 = 1.f;
        float w1 = fmaf(B0, a1, v0) + v1;
        float w2 = fmaf(B1, a1, v1) + v2;
        float w3 = fmaf(B2, a3, v2) + v3;
        A0 = v0; A1 = v1; A2 = v2; A3 = v3;
        B0 = w0; B1 = w1; B2 = w2; B3 = w3;
        ++p0; ++p1; ++p2; ++p3;
    }
    // final diag 252: only cell k=2 on lane 31 (i=126, j=126) is needed
    float f2 = fmaf(A1, p2[0], B1) + B2;
    float res = __shfl_sync(0xffffffffu, f2, 31);
    if (lane == 0) g_partial[task] = res * weight;

    // ---- last-block deterministic reduction ----
    __threadfence();
    __syncthreads();
    __shared__ unsigned int sticket;
    if (threadIdx.x == 0) sticket = atomicAdd(&g_count, 1u);
    __syncthreads();
    if (sticket == (unsigned)(gridDim.x - 1)) {
        double s = 0.0;
        for (int i = threadIdx.x; i < NTASKS; i += 32*WPC)
            s += (double)__ldcg(&g_partial[i]);
        double* ds = reinterpret_cast<double*>(smem);
        ds[threadIdx.x] = s;
        __syncthreads();
        for (int w = (32*WPC)/2; w > 0; w >>= 1) {
            if (threadIdx.x < w) ds[threadIdx.x] += ds[threadIdx.x + w];
            __syncthreads();
        }
        if (threadIdx.x == 0) {
            out[0] = (float)ds[0];
            g_count = 0;                 // re-arm for next graph replay
        }
    }
}

extern "C" void kernel_launch(void* const* d_in, const int* in_sizes, int n_in,
                              void* d_out, int out_size)
{
    const float* x = (const float*)d_in[0];
    const float* y = (const float*)d_in[1];
    (void)in_sizes; (void)n_in; (void)out_size;

    cudaFuncSetAttribute(sig_kernel,
                         cudaFuncAttributePreferredSharedMemoryCarveout, 100);

    const size_t shmem = (size_t)WPC * WSTRIDE * sizeof(float);  // 32896 B -> 7 CTAs/SM
    sig_kernel<<<NBLK, 32*WPC, shmem>>>(x, y, (float*)d_out);
}

// round 4
// speedup vs baseline: 1.8125x; 1.2411x over previous
#include <cuda_runtime.h>
#include <cuda_fp16.h>

// Signature-kernel MMD. fp16 eps table (eps = 0.25*inc, |eps| ~ 1e-2) halves
// the smem footprint: 13 CTAs/SM x 2 warps = 26 warps/SM -> single wave.
// PDE reconstructs (eps-1) once per loaded value (cvt+FADD), cells stay 2-op.
// Row stride 68 halves => lane step 33 words => conflict-free LDS.

#define BSZ 32
#define LEN 64
#define NTRI ((BSZ*(BSZ+1))/2)     // 528
#define NTASKS (2*NTRI + BSZ*BSZ)  // 2080
#define WPC 2
#define NBLK (NTASKS / WPC)        // 1040

#define RSH 68                     // row stride in halves
#define GUARDH 8
#define OSZH (31*RSH)              // odd coarse rows 1,3,..,61   (2108)
#define ESZH (32*RSH)              // even coarse rows 0,2,..,62  (2176)
#define WHALVES (GUARDH + OSZH + ESZH + 4)   // 4296 halves = 8592 B, 16B-mult

__device__ float g_partial[NTASKS];
__device__ unsigned int g_count;   // zero-init; reducer re-arms

__global__ void __launch_bounds__(32*WPC)
sig_kernel(const float* __restrict__ x, const float* __restrict__ y,
           float* __restrict__ out)
{
    extern __shared__ __align__(16) char smem[];
    const int lane = threadIdx.x & 31;
    const int wid  = threadIdx.x >> 5;
    const int task = blockIdx.x * WPC + wid;

    __half* warpbase = reinterpret_cast<__half*>(smem) + wid * WHALVES;
    __half* Ob = warpbase + GUARDH;
    __half* Eb = Ob + OSZH;

    // Zero own region + guard: all stray PDE reads must be finite.
    {
        uint4* z = reinterpret_cast<uint4*>(warpbase);
        #pragma unroll
        for (int i = lane; i < (WHALVES*2)/16; i += 32)
            z[i] = make_uint4(0u, 0u, 0u, 0u);
    }

    // ---- decode task -> pair pointers + weight ----
    const float *pa, *pb;
    float weight;
    {
        int t = task;
        if (t < 2*NTRI) {
            const float* base = (t < NTRI) ? x : y;
            if (t >= NTRI) t -= NTRI;
            int a = 0;
            while (t >= (BSZ - a)) { t -= (BSZ - a); ++a; }
            int b = a + t;
            pa = base + a*(LEN*4);
            pb = base + b*(LEN*4);
            weight = (a == b ? 1.0f : 2.0f) * (1.0f/1024.0f);
        } else {
            t -= 2*NTRI;
            pa = x + (t >> 5)*(LEN*4);
            pb = y + (t & 31)*(LEN*4);
            weight = -2.0f/1024.0f;
        }
    }

    // ---- streaming RBF gram + second differences -> eps = 0.25*inc (fp16) ----
    const int j0 = lane << 1;
    const float4 b0 = __ldg(reinterpret_cast<const float4*>(pb + 4*j0));
    const float4 b1 = __ldg(reinterpret_cast<const float4*>(pb + 4*j0 + 4));

    float g0p, g1p;
    {
        float4 a = __ldg(reinterpret_cast<const float4*>(pa));
        float d0x=a.x-b0.x, d0y=a.y-b0.y, d0z=a.z-b0.z, d0w=a.w-b0.w;
        float d1x=a.x-b1.x, d1y=a.y-b1.y, d1z=a.z-b1.z, d1w=a.w-b1.w;
        g0p = __expf(-0.5f*(d0x*d0x + d0y*d0y + d0z*d0z + d0w*d0w));
        g1p = __expf(-0.5f*(d1x*d1x + d1y*d1y + d1z*d1z + d1w*d1w));
    }
    #pragma unroll 4
    for (int u = 1; u < LEN; ++u) {
        float4 a = __ldg(reinterpret_cast<const float4*>(pa + 4*u));
        float d0x=a.x-b0.x, d0y=a.y-b0.y, d0z=a.z-b0.z, d0w=a.w-b0.w;
        float d1x=a.x-b1.x, d1y=a.y-b1.y, d1z=a.z-b1.z, d1w=a.w-b1.w;
        float g0 = __expf(-0.5f*(d0x*d0x + d0y*d0y + d0z*d0z + d0w*d0w));
        float g1 = __expf(-0.5f*(d1x*d1x + d1y*d1y + d1z*d1z + d1w*d1w));
        float t0 = g0 - g0p;
        float t1 = g1 - g1p;
        float tn = __shfl_down_sync(0xffffffffu, t0, 1);   // diff at col j0+2
        float e0 = 0.25f * (t1 - t0);                      // eps col j0
        float e1 = 0.25f * (tn - t1);                      // eps col j0+1
        int v = u - 1;
        __half* row = ((v & 1) ? Ob : Eb) + (v >> 1) * RSH;
        reinterpret_cast<__half2*>(row)[lane] = __floats2half2_rn(e0, e1);
        g0p = g0; g1p = g1;
    }
    __syncwarp();

    // ---- Goursat PDE, antidiagonal wavefront, masking-free ----
    // Lane holds cells i = 4*lane + k. Per-cell coarse row fixed; column = m + c.
    const int L = lane;
    const __half* p0 = Ob + ((L == 0) ? 0 : (66*L - 68));
    const __half* p1 = Eb + 66*L;
    const __half* p2 = Eb + 66*L - 1;
    const __half* p3 = Ob + 66*L - 1;

    float A0 = (L==0) ? 1.f : 0.f, A1 = 0.f, A2 = 0.f, A3 = 0.f;   // diag 0
    float B0 = A0, B1 = A0, B2 = 0.f, B3 = 0.f;                    // diag 1
    const bool isL0 = (L == 0);

    #pragma unroll 5
    for (int m = 0; m < 125; ++m) {
        float sh1 = __shfl_up_sync(0xffffffffu, B3, 1);
        float sh2 = __shfl_up_sync(0xffffffffu, A3, 1);
        float a0A = __half2float(p0[m])   - 1.0f;
        float a0B = __half2float(p0[m+1]) - 1.0f;
        float a1  = __half2float(p1[m])   - 1.0f;   // shared: k1 both steps, k2 B-step
        float a2  = __half2float(p2[m])   - 1.0f;
        float a3  = __half2float(p3[m])   - 1.0f;   // shared: k3 both steps
        // diag d = 2m+2
        float v0 = fmaf(sh2, a0A, sh1) + B0;  if (isL0) v0 = 1.f;
        float v1 = fmaf(A0, a1, B0) + B1;
        float v2 = fmaf(A1, a2, B1) + B2;
        float v3 = fmaf(A2, a3, B2) + B3;
        // diag d+1 = 2m+3
        float sh1b = __shfl_up_sync(0xffffffffu, v3, 1);
        float w0 = fmaf(sh1, a0B, sh1b) + v0; if (isL0) w0 = 1.f;
        float w1 = fmaf(B0, a1, v0) + v1;
        float w2 = fmaf(B1, a1, v1) + v2;
        float w3 = fmaf(B2, a3, v2) + v3;
        A0 = v0; A1 = v1; A2 = v2; A3 = v3;
        B0 = w0; B1 = w1; B2 = w2; B3 = w3;
    }
    // final diag 252: only cell k=2 on lane 31 (i=126, j=126)
    float a2f = __half2float(p2[125]) - 1.0f;
    float f2 = fmaf(A1, a2f, B1) + B2;
    float res = __shfl_sync(0xffffffffu, f2, 31);
    if (lane == 0) g_partial[task] = res * weight;

    // ---- last-block deterministic reduction ----
    __threadfence();
    __syncthreads();
    __shared__ unsigned int sticket;
    if (threadIdx.x == 0) sticket = atomicAdd(&g_count, 1u);
    __syncthreads();
    if (sticket == (unsigned)(gridDim.x - 1)) {
        double s = 0.0;
        for (int i = threadIdx.x; i < NTASKS; i += 32*WPC)
            s += (double)__ldcg(&g_partial[i]);
        double* ds = reinterpret_cast<double*>(smem);
        ds[threadIdx.x] = s;
        __syncthreads();
        for (int w = (32*WPC)/2; w > 0; w >>= 1) {
            if (threadIdx.x < w) ds[threadIdx.x] += ds[threadIdx.x + w];
            __syncthreads();
        }
        if (threadIdx.x == 0) {
            out[0] = (float)ds[0];
            g_count = 0;                 // re-arm for next graph replay
        }
    }
}

extern "C" void kernel_launch(void* const* d_in, const int* in_sizes, int n_in,
                              void* d_out, int out_size)
{
    const float* x = (const float*)d_in[0];
    const float* y = (const float*)d_in[1];
    (void)in_sizes; (void)n_in; (void)out_size;

    cudaFuncSetAttribute(sig_kernel,
                         cudaFuncAttributePreferredSharedMemoryCarveout, 100);

    const size_t shmem = (size_t)WPC * WHALVES * sizeof(__half);  // 17184 B
    sig_kernel<<<NBLK, 32*WPC, shmem>>>(x, y, (float*)d_out);
}